// round 3
// baseline (speedup 1.0000x reference)
#include <cuda_runtime.h>
#include <cstdint>
#include <mma.h>
#include <math.h>

using namespace nvcuda;

// ---------------- problem constants ----------------
#define BATCH   2
#define LIN     135000
#define DMODEL  768
#define NLAYERS 24
#define DINNER  1536
#define DSTATE  16
#define DCONV   4
#define DTRANK  48
#define KDS     32
#define SDS     32
#define LATENT  64
#define LSEQ    4218                 // (135000-32)/32 + 1
#define MREAL   (BATCH*LSEQ)         // 8436
#define MPAD    8448                 // 66 * 128

// ---------------- scratch (device globals; no allocation allowed) ----------------
__device__ float g_h    [MPAD*DMODEL];
__device__ float g_hn   [MPAD*DMODEL];
__device__ float g_xz   [MPAD*2*DINNER];
__device__ float g_u    [MPAD*DINNER];
__device__ float g_delta[MPAD*DINNER];
__device__ float g_draw [MPAD*DINNER];   // dt raw -> delta*u
__device__ float g_proj [MPAD*80];
__device__ float g_y    [MPAD*DINNER];
__device__ float g_pooled[BATCH*DMODEL];

// ---------------- cp.async helpers ----------------
__device__ __forceinline__ void cp_async16(void* dst, const void* src, int bytes) {
    unsigned int d = (unsigned int)__cvta_generic_to_shared(dst);
    asm volatile("cp.async.cg.shared.global [%0], [%1], 16, %2;\n" :: "r"(d), "l"(src), "r"(bytes));
}
__device__ __forceinline__ void cp_commit() { asm volatile("cp.async.commit_group;\n"); }
template<int W> __device__ __forceinline__ void cp_wait() { asm volatile("cp.async.wait_group %0;\n" :: "n"(W)); }

// ---------------- downsample conv: x(2,1,135000) -> h(MREAL,768) ----------------
__global__ void k_downsample(const float* __restrict__ x, const float* __restrict__ cw,
                             const float* __restrict__ cb, float* __restrict__ h) {
    int r = blockIdx.x;
    int b = r / LSEQ, t = r % LSEQ;
    __shared__ float xs[KDS];
    if (threadIdx.x < KDS) xs[threadIdx.x] = x[b*LIN + t*SDS + threadIdx.x];
    __syncthreads();
    for (int n = threadIdx.x; n < DMODEL; n += blockDim.x) {
        float acc = cb[n];
        const float* w = cw + n*KDS;
        #pragma unroll
        for (int k = 0; k < KDS; k++) acc += xs[k]*w[k];
        h[r*DMODEL + n] = acc;
    }
}

// ---------------- RMSNorm over 768 ----------------
__global__ void k_rmsnorm(const float* __restrict__ in, const float* __restrict__ w,
                          float* __restrict__ out) {
    int r = blockIdx.x;
    __shared__ float red[256];
    const float* row = in + r*DMODEL;
    float s = 0.f;
    #pragma unroll
    for (int i = 0; i < 3; i++) { float v = row[threadIdx.x + i*256]; s += v*v; }
    red[threadIdx.x] = s; __syncthreads();
    for (int o = 128; o > 0; o >>= 1) {
        if (threadIdx.x < o) red[threadIdx.x] += red[threadIdx.x + o];
        __syncthreads();
    }
    float inv = rsqrtf(red[0]/(float)DMODEL + 1e-5f);
    #pragma unroll
    for (int i = 0; i < 3; i++) {
        int d = threadIdx.x + i*256;
        out[r*DMODEL + d] = row[d]*inv*w[d];
    }
}

// ---------------- TF32 wmma GEMM: C[M,N] = A[M,K] * W[N,K]^T  ----------------
// MODE 0: plain store. MODE 1: accumulate into C. MODE 2: delta-fusion epilogue:
//   v = acc + db[n]; dl = softplus(v); delta[g]=dl; C[g]=dl*u[g]
#define BM_  128
#define BK_  32
#define LDS_ 36      // padded smem row stride (144B, multiple of 16B)

template<int BN, int WARPS_M, int WARPS_N, int MODE>
__global__ __launch_bounds__(256) void k_gemm(
    const float* __restrict__ A, int lda,
    const float* __restrict__ W, int ldw,
    float* __restrict__ C, int ldc, int N, int K,
    const float* __restrict__ db, const float* __restrict__ uu,
    float* __restrict__ dlt)
{
    extern __shared__ float smem[];
    constexpr int ASZ = BM_ * LDS_;
    constexpr int BSZ = BN  * LDS_;
    float* As0 = smem;
    float* As1 = smem + ASZ;
    float* Bs0 = smem + 2*ASZ;
    float* Bs1 = smem + 2*ASZ + BSZ;

    const int tid = threadIdx.x;
    const int rowBase = blockIdx.y * BM_;
    const int n0 = blockIdx.x * BN;

    auto load_stage = [&](float* Adst, float* Bdst, int k0) {
        #pragma unroll
        for (int i = 0; i < 4; i++) {                 // A tile: 128x32 = 1024 float4
            int idx = tid + i*256;
            int r = idx >> 3, c = (idx & 7)*4;
            int k = k0 + c;
            int rem = K - k;
            int bytes = rem >= 4 ? 16 : (rem > 0 ? rem*4 : 0);
            const float* src = bytes ? (A + (size_t)(rowBase + r)*lda + k) : A;
            cp_async16(Adst + r*LDS_ + c, src, bytes);
        }
        constexpr int BCH = BN*8/256;
        #pragma unroll
        for (int i = 0; i < BCH; i++) {               // B tile: BN x 32
            int idx = tid + i*256;
            int r = idx >> 3, c = (idx & 7)*4;
            int k = k0 + c;
            int n = n0 + r;
            int rem = K - k;
            int bytes = (n < N) ? (rem >= 4 ? 16 : (rem > 0 ? rem*4 : 0)) : 0;
            const float* src = bytes ? (W + (size_t)n*ldw + k) : W;
            cp_async16(Bdst + r*LDS_ + c, src, bytes);
        }
    };

    constexpr int WTM = BM_/WARPS_M;
    constexpr int WTN = BN/WARPS_N;
    constexpr int MI  = WTM/16;
    constexpr int NI  = WTN/16;
    const int warpId = tid >> 5;
    const int wm = warpId / WARPS_N;
    const int wn = warpId % WARPS_N;

    wmma::fragment<wmma::accumulator,16,16,8,float> cf[MI][NI];
    #pragma unroll
    for (int i = 0; i < MI; i++)
        #pragma unroll
        for (int j = 0; j < NI; j++) wmma::fill_fragment(cf[i][j], 0.f);

    const int ktiles = (K + BK_ - 1)/BK_;
    load_stage(As0, Bs0, 0);
    cp_commit();
    for (int kt = 0; kt < ktiles; kt++) {
        if (kt + 1 < ktiles) {
            load_stage((kt&1)?As0:As1, (kt&1)?Bs0:Bs1, (kt+1)*BK_);
            cp_commit();
            cp_wait<1>();
        } else {
            cp_wait<0>();
        }
        __syncthreads();
        const float* a = (kt&1)?As1:As0;
        const float* b = (kt&1)?Bs1:Bs0;
        #pragma unroll
        for (int kk = 0; kk < BK_; kk += 8) {
            wmma::fragment<wmma::matrix_a,16,16,8,wmma::precision::tf32,wmma::row_major> af[MI];
            wmma::fragment<wmma::matrix_b,16,16,8,wmma::precision::tf32,wmma::col_major> bf[NI];
            #pragma unroll
            for (int i = 0; i < MI; i++) {
                wmma::load_matrix_sync(af[i], a + (wm*WTM + i*16)*LDS_ + kk, LDS_);
                #pragma unroll
                for (int e = 0; e < af[i].num_elements; e++)
                    af[i].x[e] = wmma::__float_to_tf32(af[i].x[e]);
            }
            #pragma unroll
            for (int j = 0; j < NI; j++) {
                wmma::load_matrix_sync(bf[j], b + (wn*WTN + j*16)*LDS_ + kk, LDS_);
                #pragma unroll
                for (int e = 0; e < bf[j].num_elements; e++)
                    bf[j].x[e] = wmma::__float_to_tf32(bf[j].x[e]);
            }
            #pragma unroll
            for (int i = 0; i < MI; i++)
                #pragma unroll
                for (int j = 0; j < NI; j++)
                    wmma::mma_sync(cf[i][j], af[i], bf[j], cf[i][j]);
        }
        __syncthreads();
    }

    if constexpr (MODE == 2) {
        constexpr int CLD2 = BN + 4;
        float* Cs = smem;
        #pragma unroll
        for (int i = 0; i < MI; i++)
            #pragma unroll
            for (int j = 0; j < NI; j++)
                wmma::store_matrix_sync(Cs + (wm*WTM + i*16)*CLD2 + wn*WTN + j*16,
                                        cf[i][j], CLD2, wmma::mem_row_major);
        __syncthreads();
        #pragma unroll
        for (int it = 0; it < BM_*BN/256; it++) {
            int idx = tid + it*256;
            int r = idx / BN, c = idx % BN;
            size_t g = (size_t)(rowBase + r)*ldc + n0 + c;
            float v = Cs[r*CLD2 + c] + db[n0 + c];
            float dl = (v > 20.f) ? v : log1pf(__expf(v));
            dlt[g] = dl;
            C[g]   = dl * uu[g];
        }
    } else {
        #pragma unroll
        for (int i = 0; i < MI; i++) {
            int r = rowBase + wm*WTM + i*16;
            #pragma unroll
            for (int j = 0; j < NI; j++) {
                int n = n0 + wn*WTN + j*16;
                if (n < N) {
                    float* ptr = C + (size_t)r*ldc + n;
                    if constexpr (MODE == 1) {
                        wmma::fragment<wmma::accumulator,16,16,8,float> of;
                        wmma::load_matrix_sync(of, ptr, ldc, wmma::mem_row_major);
                        #pragma unroll
                        for (int e = 0; e < of.num_elements; e++) cf[i][j].x[e] += of.x[e];
                    }
                    wmma::store_matrix_sync(ptr, cf[i][j], ldc, wmma::mem_row_major);
                }
            }
        }
    }
}

// ---------------- causal depthwise conv1d (width 4) + silu ----------------
__global__ void k_conv1d_silu(const float* __restrict__ xz, const float* __restrict__ w,
                              const float* __restrict__ bias, float* __restrict__ u) {
    int idx = blockIdx.x*blockDim.x + threadIdx.x;
    const int D4 = DINNER/4;
    if (idx >= MREAL*D4) return;
    int r  = idx / D4;
    int d4 = (idx % D4)*4;
    int t  = r % LSEQ;
    float4 w0 = *(const float4*)(w + (d4+0)*DCONV);
    float4 w1 = *(const float4*)(w + (d4+1)*DCONV);
    float4 w2 = *(const float4*)(w + (d4+2)*DCONV);
    float4 w3 = *(const float4*)(w + (d4+3)*DCONV);
    const float* w0p = &w0.x; const float* w1p = &w1.x;
    const float* w2p = &w2.x; const float* w3p = &w3.x;
    float4 acc = make_float4(bias[d4], bias[d4+1], bias[d4+2], bias[d4+3]);
    #pragma unroll
    for (int j = 0; j < DCONV; j++) {
        int tt = t + j - (DCONV-1);
        if (tt < 0) continue;
        float4 v = *(const float4*)(xz + (size_t)(r + j - (DCONV-1))*(2*DINNER) + d4);
        acc.x += v.x * w0p[j];
        acc.y += v.y * w1p[j];
        acc.z += v.z * w2p[j];
        acc.w += v.w * w3p[j];
    }
    acc.x = acc.x / (1.f + __expf(-acc.x));
    acc.y = acc.y / (1.f + __expf(-acc.y));
    acc.z = acc.z / (1.f + __expf(-acc.z));
    acc.w = acc.w / (1.f + __expf(-acc.w));
    *(float4*)(u + (size_t)r*DINNER + d4) = acc;
}

// ---------------- selective scan: 16 lanes per (b,d) chain ----------------
__global__ void k_scan(const float* __restrict__ delta, const float* __restrict__ du,
                       const float* __restrict__ proj,  const float* __restrict__ u,
                       const float* __restrict__ xz,    const float* __restrict__ Alog,
                       const float* __restrict__ Dskip, float* __restrict__ y) {
    int chain = blockIdx.x*(blockDim.x/16) + (threadIdx.x >> 4);
    int s = threadIdx.x & 15;
    int b = chain / DINNER, d = chain % DINNER;
    float Av = -expf(Alog[d*DSTATE + s]);
    float Dv = Dskip[d];
    bool lane0 = (s == 0);
    float h = 0.f;
    int rbase = b*LSEQ;

    int t = 0;
    for (; t + 4 <= LSEQ; t += 4) {
        float dl[4], db_[4], bv[4], cv[4], uv[4], zv[4];
        #pragma unroll
        for (int j = 0; j < 4; j++) {
            int r = rbase + t + j;
            dl[j]  = delta[(size_t)r*DINNER + d];
            db_[j] = du  [(size_t)r*DINNER + d];
            bv[j]  = proj[(size_t)r*80 + 48 + s];
            cv[j]  = proj[(size_t)r*80 + 64 + s];
            if (lane0) {
                uv[j] = u [(size_t)r*DINNER + d];
                zv[j] = xz[(size_t)r*2*DINNER + DINNER + d];
            }
        }
        #pragma unroll
        for (int j = 0; j < 4; j++) {
            h = __expf(dl[j]*Av)*h + db_[j]*bv[j];
            float yv = h*cv[j];
            yv += __shfl_xor_sync(0xffffffffu, yv, 8);
            yv += __shfl_xor_sync(0xffffffffu, yv, 4);
            yv += __shfl_xor_sync(0xffffffffu, yv, 2);
            yv += __shfl_xor_sync(0xffffffffu, yv, 1);
            if (lane0) {
                float z = zv[j];
                float sig = 1.f/(1.f + __expf(-z));
                y[(size_t)(rbase + t + j)*DINNER + d] = (yv + uv[j]*Dv) * z * sig;
            }
        }
    }
    for (; t < LSEQ; t++) {
        int r = rbase + t;
        float dl  = delta[(size_t)r*DINNER + d];
        float db_ = du  [(size_t)r*DINNER + d];
        float bv  = proj[(size_t)r*80 + 48 + s];
        float cv  = proj[(size_t)r*80 + 64 + s];
        h = __expf(dl*Av)*h + db_*bv;
        float yv = h*cv;
        yv += __shfl_xor_sync(0xffffffffu, yv, 8);
        yv += __shfl_xor_sync(0xffffffffu, yv, 4);
        yv += __shfl_xor_sync(0xffffffffu, yv, 2);
        yv += __shfl_xor_sync(0xffffffffu, yv, 1);
        if (lane0) {
            float uvv = u [(size_t)r*DINNER + d];
            float z   = xz[(size_t)r*2*DINNER + DINNER + d];
            float sig = 1.f/(1.f + __expf(-z));
            y[(size_t)r*DINNER + d] = (yv + uvv*Dv) * z * sig;
        }
    }
}

// ---------------- final pooling + head ----------------
__global__ void k_zero(float* p, int n) {
    int i = blockIdx.x*blockDim.x + threadIdx.x;
    if (i < n) p[i] = 0.f;
}

__global__ void k_pool(const float* __restrict__ hn, float* __restrict__ pooled) {
    int d  = blockIdx.x*blockDim.x + threadIdx.x;
    int b  = blockIdx.y;
    int tc = blockIdx.z;
    int t0 = tc*132, t1 = t0 + 132; if (t1 > LSEQ) t1 = LSEQ;
    float acc = 0.f;
    for (int t = t0; t < t1; t++) acc += hn[(size_t)(b*LSEQ + t)*DMODEL + d];
    atomicAdd(&pooled[b*DMODEL + d], acc);
}

__global__ void k_head(const float* __restrict__ pooled, const float* __restrict__ pw,
                       const float* __restrict__ pb, const float* __restrict__ lw,
                       const float* __restrict__ lb, float* __restrict__ out) {
    int b = blockIdx.x, j = threadIdx.x;
    __shared__ float zs[LATENT];
    const float* pr = pooled + b*DMODEL;
    const float* wr = pw + j*DMODEL;
    float acc = 0.f;
    for (int d = 0; d < DMODEL; d++) acc += pr[d]*wr[d];
    float zed = acc*(1.f/(float)LSEQ) + pb[j];
    zs[j] = zed; __syncthreads();
    float mu = 0.f;
    for (int i = 0; i < LATENT; i++) mu += zs[i];
    mu /= LATENT;
    float var = 0.f;
    for (int i = 0; i < LATENT; i++) { float dd = zs[i]-mu; var += dd*dd; }
    var /= LATENT;
    out[b*LATENT + j] = (zed - mu)*rsqrtf(var + 1e-5f)*lw[j] + lb[j];
}

// ---------------- host orchestration ----------------
#define SMEM_BIG    (2*(128*LDS_ + 128*LDS_)*4)   // 73728 B
#define SMEM_NARROW (2*(128*LDS_ +  64*LDS_)*4)   // 55296 B

extern "C" void kernel_launch(void* const* d_in, const int* in_sizes, int n_in,
                              void* d_out, int out_size) {
    const float* x         = (const float*)d_in[0];
    const float* conv_w    = (const float*)d_in[1];
    const float* conv_b    = (const float*)d_in[2];
    const float* norm_w    = (const float*)d_in[3];
    const float* in_proj_w = (const float*)d_in[4];
    const float* conv1d_w  = (const float*)d_in[5];
    const float* conv1d_b  = (const float*)d_in[6];
    const float* x_proj_w  = (const float*)d_in[7];
    const float* dt_proj_w = (const float*)d_in[8];
    const float* dt_proj_b = (const float*)d_in[9];
    const float* A_log     = (const float*)d_in[10];
    const float* D_skip    = (const float*)d_in[11];
    const float* out_proj_w= (const float*)d_in[12];
    const float* norm_f_w  = (const float*)d_in[13];
    const float* proj_w    = (const float*)d_in[14];
    const float* proj_b    = (const float*)d_in[15];
    const float* ln_w      = (const float*)d_in[16];
    const float* ln_b      = (const float*)d_in[17];

    float *h, *hn, *xz, *u, *delta, *draw, *proj, *y, *pooled;
    cudaGetSymbolAddress((void**)&h,      g_h);
    cudaGetSymbolAddress((void**)&hn,     g_hn);
    cudaGetSymbolAddress((void**)&xz,     g_xz);
    cudaGetSymbolAddress((void**)&u,      g_u);
    cudaGetSymbolAddress((void**)&delta,  g_delta);
    cudaGetSymbolAddress((void**)&draw,   g_draw);
    cudaGetSymbolAddress((void**)&proj,   g_proj);
    cudaGetSymbolAddress((void**)&y,      g_y);
    cudaGetSymbolAddress((void**)&pooled, g_pooled);

    cudaFuncSetAttribute(k_gemm<128,2,4,0>, cudaFuncAttributeMaxDynamicSharedMemorySize, SMEM_BIG);
    cudaFuncSetAttribute(k_gemm<128,2,4,1>, cudaFuncAttributeMaxDynamicSharedMemorySize, SMEM_BIG);
    cudaFuncSetAttribute(k_gemm<128,2,4,2>, cudaFuncAttributeMaxDynamicSharedMemorySize, SMEM_BIG);
    cudaFuncSetAttribute(k_gemm<64,4,2,0>,  cudaFuncAttributeMaxDynamicSharedMemorySize, SMEM_NARROW);

    k_downsample<<<MREAL, 128>>>(x, conv_w, conv_b, h);

    const int convThreads = 256;
    const int convBlocks  = (MREAL*(DINNER/4) + convThreads - 1)/convThreads;

    for (int l = 0; l < NLAYERS; l++) {
        k_rmsnorm<<<MREAL, 256>>>(h, norm_w + (size_t)l*DMODEL, hn);

        // in_proj: xz[M,3072] = hn[M,768] * W[3072,768]^T
        k_gemm<128,2,4,0><<<dim3(2*DINNER/128, MPAD/128), 256, SMEM_BIG>>>(
            hn, DMODEL, in_proj_w + (size_t)l*2*DINNER*DMODEL, DMODEL,
            xz, 2*DINNER, 2*DINNER, DMODEL, nullptr, nullptr, nullptr);

        k_conv1d_silu<<<convBlocks, convThreads>>>(xz, conv1d_w + (size_t)l*DINNER*DCONV,
                                                   conv1d_b + (size_t)l*DINNER, u);

        // x_proj: proj[M,80] = u[M,1536] * W[80,1536]^T
        k_gemm<64,4,2,0><<<dim3(2, MPAD/128), 256, SMEM_NARROW>>>(
            u, DINNER, x_proj_w + (size_t)l*80*DINNER, DINNER,
            proj, 80, 80, DINNER, nullptr, nullptr, nullptr);

        // dt_proj + fused softplus: delta, draw = f(proj[:, :48] * W[1536,48]^T)
        k_gemm<128,2,4,2><<<dim3(DINNER/128, MPAD/128), 256, SMEM_BIG>>>(
            proj, 80, dt_proj_w + (size_t)l*DINNER*DTRANK, DTRANK,
            draw, DINNER, DINNER, DTRANK,
            dt_proj_b + (size_t)l*DINNER, u, delta);

        k_scan<<<(BATCH*DINNER)/8, 128>>>(delta, draw, proj, u, xz,
                                          A_log + (size_t)l*DINNER*DSTATE,
                                          D_skip + (size_t)l*DINNER, y);

        // out_proj (+residual): h += y[M,1536] * W[768,1536]^T
        k_gemm<128,2,4,1><<<dim3(DMODEL/128, MPAD/128), 256, SMEM_BIG>>>(
            y, DINNER, out_proj_w + (size_t)l*DMODEL*DINNER, DINNER,
            h, DMODEL, DMODEL, DINNER, nullptr, nullptr, nullptr);
    }

    k_rmsnorm<<<MREAL, 256>>>(h, norm_f_w, hn);
    k_zero<<<(BATCH*DMODEL + 255)/256, 256>>>(pooled, BATCH*DMODEL);
    k_pool<<<dim3(3, BATCH, 32), 256>>>(hn, pooled);
    k_head<<<BATCH, LATENT>>>(pooled, proj_w, proj_b, ln_w, ln_b, (float*)d_out);
}

// round 4
// speedup vs baseline: 1.4563x; 1.4563x over previous
#include <cuda_runtime.h>
#include <cstdint>
#include <cuda_fp16.h>
#include <mma.h>
#include <math.h>

using namespace nvcuda;

// ---------------- problem constants ----------------
#define BATCH   2
#define LIN     135000
#define DMODEL  768
#define NLAYERS 24
#define DINNER  1536
#define DSTATE  16
#define DCONV   4
#define DTRANK  48
#define KDS     32
#define SDS     32
#define LATENT  64
#define LSEQ    4218
#define MREAL   (BATCH*LSEQ)         // 8436
#define MPAD    8448                 // 66 * 128

// ---------------- scratch (device globals) ----------------
__device__ float  g_h    [MPAD*DMODEL];
__device__ float  g_hn   [MPAD*DMODEL];     // final norm (fp32, for pooling)
__device__ __half g_hnh  [MPAD*DMODEL];     // per-layer norm (fp16 GEMM A)
__device__ float  g_xz   [MPAD*2*DINNER];
__device__ float  g_u    [MPAD*DINNER];
__device__ __half g_uh   [MPAD*DINNER];
__device__ float  g_delta[MPAD*DINNER];
__device__ float  g_draw [MPAD*DINNER];     // delta*u
__device__ float  g_proj [MPAD*80];
__device__ __half g_projh[MPAD*80];
__device__ __half g_yh   [MPAD*DINNER];
__device__ float  g_pooled[BATCH*DMODEL];
// fp16 weights (converted each launch)
__device__ __half g_wih[NLAYERS*2*DINNER*DMODEL];   // in_proj
__device__ __half g_wxh[NLAYERS*80*DINNER];         // x_proj
__device__ __half g_wdh[NLAYERS*DINNER*DTRANK];     // dt_proj
__device__ __half g_woh[NLAYERS*DMODEL*DINNER];     // out_proj

// ---------------- cp.async helpers ----------------
__device__ __forceinline__ void cp_async16(void* dst, const void* src, int bytes) {
    unsigned int d = (unsigned int)__cvta_generic_to_shared(dst);
    asm volatile("cp.async.cg.shared.global [%0], [%1], 16, %2;\n" :: "r"(d), "l"(src), "r"(bytes));
}
__device__ __forceinline__ void cp_commit() { asm volatile("cp.async.commit_group;\n"); }
template<int W> __device__ __forceinline__ void cp_wait() { asm volatile("cp.async.wait_group %0;\n" :: "n"(W)); }

// ---------------- fp32 -> fp16 convert ----------------
__global__ void k_f2h(const float* __restrict__ src, __half* __restrict__ dst, int n) {
    int i = (blockIdx.x*blockDim.x + threadIdx.x)*4;
    if (i + 3 < n) {
        float4 v = *(const float4*)(src + i);
        __half2* o = (__half2*)(dst + i);
        o[0] = __floats2half2_rn(v.x, v.y);
        o[1] = __floats2half2_rn(v.z, v.w);
    } else {
        for (; i < n; i++) dst[i] = __float2half(src[i]);
    }
}

// ---------------- downsample conv ----------------
__global__ void k_downsample(const float* __restrict__ x, const float* __restrict__ cw,
                             const float* __restrict__ cb, float* __restrict__ h) {
    int r = blockIdx.x;
    int b = r / LSEQ, t = r % LSEQ;
    __shared__ float xs[KDS];
    if (threadIdx.x < KDS) xs[threadIdx.x] = x[b*LIN + t*SDS + threadIdx.x];
    __syncthreads();
    for (int n = threadIdx.x; n < DMODEL; n += blockDim.x) {
        float acc = cb[n];
        const float* w = cw + n*KDS;
        #pragma unroll
        for (int k = 0; k < KDS; k++) acc += xs[k]*w[k];
        h[r*DMODEL + n] = acc;
    }
}

// ---------------- RMSNorm over 768 (T = __half or float output) ----------------
template<typename T>
__global__ void k_rmsnorm(const float* __restrict__ in, const float* __restrict__ w,
                          T* __restrict__ out) {
    int r = blockIdx.x;
    __shared__ float red[256];
    const float* row = in + (size_t)r*DMODEL;
    float s = 0.f;
    #pragma unroll
    for (int i = 0; i < 3; i++) { float v = row[threadIdx.x + i*256]; s += v*v; }
    red[threadIdx.x] = s; __syncthreads();
    for (int o = 128; o > 0; o >>= 1) {
        if (threadIdx.x < o) red[threadIdx.x] += red[threadIdx.x + o];
        __syncthreads();
    }
    float inv = rsqrtf(red[0]/(float)DMODEL + 1e-5f);
    #pragma unroll
    for (int i = 0; i < 3; i++) {
        int d = threadIdx.x + i*256;
        out[(size_t)r*DMODEL + d] = (T)(row[d]*inv*w[d]);
    }
}

// ---------------- fp16 wmma GEMM: C[M,N] = A[M,K] * W[N,K]^T ----------------
// MODE 0: store fp32 C (+ optional fp16 copy Ch). MODE 1: C += . MODE 2: dt fusion.
#define BM_  128
#define BK_  64
#define LDH_ 72      // smem row stride in halves (144B, 16B multiple)

template<int BN, int MODE>
__global__ __launch_bounds__(256) void k_gemmh(
    const __half* __restrict__ A, int lda,
    const __half* __restrict__ W, int ldw,
    float* __restrict__ C, int ldc, int N, int K,
    const float* __restrict__ db, const float* __restrict__ uu,
    float* __restrict__ dlt, __half* __restrict__ Ch)
{
    extern __shared__ char smraw[];
    __half* smem = (__half*)smraw;
    constexpr int ASZ = BM_ * LDH_;
    constexpr int BSZ = BN  * LDH_;
    __half* As0 = smem;
    __half* As1 = smem + ASZ;
    __half* Bs0 = smem + 2*ASZ;
    __half* Bs1 = smem + 2*ASZ + BSZ;

    const int tid = threadIdx.x;
    const int rowBase = blockIdx.y * BM_;
    const int n0 = blockIdx.x * BN;

    auto load_stage = [&](__half* Adst, __half* Bdst, int k0) {
        #pragma unroll
        for (int i = 0; i < 4; i++) {                 // A: 128 x 64 halves = 1024 x 16B
            int idx = tid + i*256;
            int r = idx >> 3, c = (idx & 7)*8;
            int k = k0 + c;
            int bytes = (k < K) ? 16 : 0;
            const __half* src = bytes ? (A + (size_t)(rowBase + r)*lda + k) : A;
            cp_async16(Adst + r*LDH_ + c, src, bytes);
        }
        constexpr int BCH = BN*8/256;
        #pragma unroll
        for (int i = 0; i < BCH; i++) {               // B: BN x 64 halves
            int idx = tid + i*256;
            int r = idx >> 3, c = (idx & 7)*8;
            int k = k0 + c, n = n0 + r;
            int bytes = (n < N && k < K) ? 16 : 0;
            const __half* src = bytes ? (W + (size_t)n*ldw + k) : W;
            cp_async16(Bdst + r*LDH_ + c, src, bytes);
        }
    };

    constexpr int WARPS_N = (BN == 128) ? 4 : 2;      // 8 warps total
    constexpr int WARPS_M = 8/WARPS_N;
    constexpr int WTM = BM_/WARPS_M;                  // 64 (BN=128) / 32 (BN=64)
    constexpr int WTN = BN/WARPS_N;                   // 32
    constexpr int MI = WTM/16, NI = WTN/16;
    const int warpId = tid >> 5;
    const int wm = warpId / WARPS_N;
    const int wn = warpId % WARPS_N;

    wmma::fragment<wmma::accumulator,16,16,16,float> cf[MI][NI];
    #pragma unroll
    for (int i = 0; i < MI; i++)
        #pragma unroll
        for (int j = 0; j < NI; j++) wmma::fill_fragment(cf[i][j], 0.f);

    const int ktiles = (K + BK_ - 1)/BK_;
    load_stage(As0, Bs0, 0);
    cp_commit();
    for (int kt = 0; kt < ktiles; kt++) {
        if (kt + 1 < ktiles) {
            load_stage((kt&1)?As0:As1, (kt&1)?Bs0:Bs1, (kt+1)*BK_);
            cp_commit();
            cp_wait<1>();
        } else {
            cp_wait<0>();
        }
        __syncthreads();
        const __half* a = (kt&1)?As1:As0;
        const __half* b = (kt&1)?Bs1:Bs0;
        #pragma unroll
        for (int kk = 0; kk < BK_; kk += 16) {
            wmma::fragment<wmma::matrix_a,16,16,16,__half,wmma::row_major> af[MI];
            wmma::fragment<wmma::matrix_b,16,16,16,__half,wmma::col_major> bf[NI];
            #pragma unroll
            for (int i = 0; i < MI; i++)
                wmma::load_matrix_sync(af[i], a + (wm*WTM + i*16)*LDH_ + kk, LDH_);
            #pragma unroll
            for (int j = 0; j < NI; j++)
                wmma::load_matrix_sync(bf[j], b + (wn*WTN + j*16)*LDH_ + kk, LDH_);
            #pragma unroll
            for (int i = 0; i < MI; i++)
                #pragma unroll
                for (int j = 0; j < NI; j++)
                    wmma::mma_sync(cf[i][j], af[i], bf[j], cf[i][j]);
        }
        __syncthreads();
    }

    // ---- smem-staged coalesced epilogue ----
    constexpr int CLD = BN + 4;
    float* Cs = (float*)smraw;
    #pragma unroll
    for (int i = 0; i < MI; i++)
        #pragma unroll
        for (int j = 0; j < NI; j++)
            wmma::store_matrix_sync(Cs + (wm*WTM + i*16)*CLD + wn*WTN + j*16,
                                    cf[i][j], CLD, wmma::mem_row_major);
    __syncthreads();

    constexpr int IT = BM_*BN/(256*4);
    #pragma unroll
    for (int it = 0; it < IT; it++) {
        int idx = tid + it*256;
        int r = idx / (BN/4), c4 = (idx % (BN/4))*4;
        int n = n0 + c4;
        if (n >= N) continue;
        size_t g = (size_t)(rowBase + r)*ldc + n;
        float4 v = *(float4*)(Cs + r*CLD + c4);
        if constexpr (MODE == 1) {
            float4 o = *(float4*)(C + g);
            v.x += o.x; v.y += o.y; v.z += o.z; v.w += o.w;
            *(float4*)(C + g) = v;
        } else if constexpr (MODE == 2) {
            float4 bb = *(const float4*)(db + n);
            float4 uv = *(const float4*)(uu + g);
            float a0 = v.x + bb.x, a1 = v.y + bb.y, a2 = v.z + bb.z, a3 = v.w + bb.w;
            float d0 = (a0 > 20.f) ? a0 : log1pf(__expf(a0));
            float d1 = (a1 > 20.f) ? a1 : log1pf(__expf(a1));
            float d2 = (a2 > 20.f) ? a2 : log1pf(__expf(a2));
            float d3 = (a3 > 20.f) ? a3 : log1pf(__expf(a3));
            *(float4*)(dlt + g) = make_float4(d0, d1, d2, d3);
            *(float4*)(C + g)   = make_float4(d0*uv.x, d1*uv.y, d2*uv.z, d3*uv.w);
        } else {
            *(float4*)(C + g) = v;
            if (Ch) {
                __half2* o = (__half2*)(Ch + g);
                o[0] = __floats2half2_rn(v.x, v.y);
                o[1] = __floats2half2_rn(v.z, v.w);
            }
        }
    }
}

// ---------------- causal depthwise conv1d + silu (fp32 + fp16 out) ----------------
__global__ void k_conv1d_silu(const float* __restrict__ xz, const float* __restrict__ w,
                              const float* __restrict__ bias, float* __restrict__ u,
                              __half* __restrict__ uh) {
    int idx = blockIdx.x*blockDim.x + threadIdx.x;
    const int D4 = DINNER/4;
    if (idx >= MREAL*D4) return;
    int r  = idx / D4;
    int d4 = (idx % D4)*4;
    int t  = r % LSEQ;
    float4 w0 = *(const float4*)(w + (d4+0)*DCONV);
    float4 w1 = *(const float4*)(w + (d4+1)*DCONV);
    float4 w2 = *(const float4*)(w + (d4+2)*DCONV);
    float4 w3 = *(const float4*)(w + (d4+3)*DCONV);
    const float* w0p = &w0.x; const float* w1p = &w1.x;
    const float* w2p = &w2.x; const float* w3p = &w3.x;
    float4 acc = make_float4(bias[d4], bias[d4+1], bias[d4+2], bias[d4+3]);
    #pragma unroll
    for (int j = 0; j < DCONV; j++) {
        int tt = t + j - (DCONV-1);
        if (tt < 0) continue;
        float4 v = *(const float4*)(xz + (size_t)(r + j - (DCONV-1))*(2*DINNER) + d4);
        acc.x += v.x * w0p[j];
        acc.y += v.y * w1p[j];
        acc.z += v.z * w2p[j];
        acc.w += v.w * w3p[j];
    }
    acc.x = acc.x / (1.f + __expf(-acc.x));
    acc.y = acc.y / (1.f + __expf(-acc.y));
    acc.z = acc.z / (1.f + __expf(-acc.z));
    acc.w = acc.w / (1.f + __expf(-acc.w));
    *(float4*)(u + (size_t)r*DINNER + d4) = acc;
    __half2* o = (__half2*)(uh + (size_t)r*DINNER + d4);
    o[0] = __floats2half2_rn(acc.x, acc.y);
    o[1] = __floats2half2_rn(acc.z, acc.w);
}

// ---------------- selective scan ----------------
__global__ void k_scan(const float* __restrict__ delta, const float* __restrict__ du,
                       const float* __restrict__ proj,  const float* __restrict__ u,
                       const float* __restrict__ xz,    const float* __restrict__ Alog,
                       const float* __restrict__ Dskip, __half* __restrict__ y) {
    int chain = blockIdx.x*(blockDim.x/16) + (threadIdx.x >> 4);
    int s = threadIdx.x & 15;
    int b = chain / DINNER, d = chain % DINNER;
    float Av = -expf(Alog[d*DSTATE + s]);
    float Dv = Dskip[d];
    bool lane0 = (s == 0);
    float h = 0.f;
    int rbase = b*LSEQ;

    int t = 0;
    for (; t + 4 <= LSEQ; t += 4) {
        float dl[4], db_[4], bv[4], cv[4], uv[4], zv[4];
        #pragma unroll
        for (int j = 0; j < 4; j++) {
            int r = rbase + t + j;
            dl[j]  = delta[(size_t)r*DINNER + d];
            db_[j] = du  [(size_t)r*DINNER + d];
            bv[j]  = proj[(size_t)r*80 + 48 + s];
            cv[j]  = proj[(size_t)r*80 + 64 + s];
            if (lane0) {
                uv[j] = u [(size_t)r*DINNER + d];
                zv[j] = xz[(size_t)r*2*DINNER + DINNER + d];
            }
        }
        #pragma unroll
        for (int j = 0; j < 4; j++) {
            h = __expf(dl[j]*Av)*h + db_[j]*bv[j];
            float yv = h*cv[j];
            yv += __shfl_xor_sync(0xffffffffu, yv, 8);
            yv += __shfl_xor_sync(0xffffffffu, yv, 4);
            yv += __shfl_xor_sync(0xffffffffu, yv, 2);
            yv += __shfl_xor_sync(0xffffffffu, yv, 1);
            if (lane0) {
                float z = zv[j];
                float sig = 1.f/(1.f + __expf(-z));
                y[(size_t)(rbase + t + j)*DINNER + d] = __float2half((yv + uv[j]*Dv)*z*sig);
            }
        }
    }
    for (; t < LSEQ; t++) {
        int r = rbase + t;
        float dl  = delta[(size_t)r*DINNER + d];
        float db_ = du  [(size_t)r*DINNER + d];
        float bv  = proj[(size_t)r*80 + 48 + s];
        float cv  = proj[(size_t)r*80 + 64 + s];
        h = __expf(dl*Av)*h + db_*bv;
        float yv = h*cv;
        yv += __shfl_xor_sync(0xffffffffu, yv, 8);
        yv += __shfl_xor_sync(0xffffffffu, yv, 4);
        yv += __shfl_xor_sync(0xffffffffu, yv, 2);
        yv += __shfl_xor_sync(0xffffffffu, yv, 1);
        if (lane0) {
            float uvv = u [(size_t)r*DINNER + d];
            float z   = xz[(size_t)r*2*DINNER + DINNER + d];
            float sig = 1.f/(1.f + __expf(-z));
            y[(size_t)r*DINNER + d] = __float2half((yv + uvv*Dv)*z*sig);
        }
    }
}

// ---------------- pooling + head ----------------
__global__ void k_zero(float* p, int n) {
    int i = blockIdx.x*blockDim.x + threadIdx.x;
    if (i < n) p[i] = 0.f;
}

__global__ void k_pool(const float* __restrict__ hn, float* __restrict__ pooled) {
    int d  = blockIdx.x*blockDim.x + threadIdx.x;
    int b  = blockIdx.y;
    int tc = blockIdx.z;
    int t0 = tc*132, t1 = t0 + 132; if (t1 > LSEQ) t1 = LSEQ;
    float acc = 0.f;
    for (int t = t0; t < t1; t++) acc += hn[(size_t)(b*LSEQ + t)*DMODEL + d];
    atomicAdd(&pooled[b*DMODEL + d], acc);
}

__global__ void k_head(const float* __restrict__ pooled, const float* __restrict__ pw,
                       const float* __restrict__ pb, const float* __restrict__ lw,
                       const float* __restrict__ lb, float* __restrict__ out) {
    int b = blockIdx.x, j = threadIdx.x;
    __shared__ float zs[LATENT];
    const float* pr = pooled + b*DMODEL;
    const float* wr = pw + j*DMODEL;
    float acc = 0.f;
    for (int d = 0; d < DMODEL; d++) acc += pr[d]*wr[d];
    float zed = acc*(1.f/(float)LSEQ) + pb[j];
    zs[j] = zed; __syncthreads();
    float mu = 0.f;
    for (int i = 0; i < LATENT; i++) mu += zs[i];
    mu /= LATENT;
    float var = 0.f;
    for (int i = 0; i < LATENT; i++) { float dd = zs[i]-mu; var += dd*dd; }
    var /= LATENT;
    out[b*LATENT + j] = (zed - mu)*rsqrtf(var + 1e-5f)*lw[j] + lb[j];
}

// ---------------- host orchestration ----------------
#define SMEM_128 (2*(128*LDH_ + 128*LDH_)*2)   // 73728 B (>= 128x132x4 stage)
#define SMEM_64  (2*(128*LDH_ +  64*LDH_)*2)   // 55296 B

extern "C" void kernel_launch(void* const* d_in, const int* in_sizes, int n_in,
                              void* d_out, int out_size) {
    const float* x         = (const float*)d_in[0];
    const float* conv_w    = (const float*)d_in[1];
    const float* conv_b    = (const float*)d_in[2];
    const float* norm_w    = (const float*)d_in[3];
    const float* in_proj_w = (const float*)d_in[4];
    const float* conv1d_w  = (const float*)d_in[5];
    const float* conv1d_b  = (const float*)d_in[6];
    const float* x_proj_w  = (const float*)d_in[7];
    const float* dt_proj_w = (const float*)d_in[8];
    const float* dt_proj_b = (const float*)d_in[9];
    const float* A_log     = (const float*)d_in[10];
    const float* D_skip    = (const float*)d_in[11];
    const float* out_proj_w= (const float*)d_in[12];
    const float* norm_f_w  = (const float*)d_in[13];
    const float* proj_w    = (const float*)d_in[14];
    const float* proj_b    = (const float*)d_in[15];
    const float* ln_w      = (const float*)d_in[16];
    const float* ln_b      = (const float*)d_in[17];

    float  *h, *hn, *xz, *u, *delta, *draw, *proj, *pooled;
    __half *hnh, *uh, *projh, *yh, *wih, *wxh, *wdh, *woh;
    cudaGetSymbolAddress((void**)&h,      g_h);
    cudaGetSymbolAddress((void**)&hn,     g_hn);
    cudaGetSymbolAddress((void**)&hnh,    g_hnh);
    cudaGetSymbolAddress((void**)&xz,     g_xz);
    cudaGetSymbolAddress((void**)&u,      g_u);
    cudaGetSymbolAddress((void**)&uh,     g_uh);
    cudaGetSymbolAddress((void**)&delta,  g_delta);
    cudaGetSymbolAddress((void**)&draw,   g_draw);
    cudaGetSymbolAddress((void**)&proj,   g_proj);
    cudaGetSymbolAddress((void**)&projh,  g_projh);
    cudaGetSymbolAddress((void**)&yh,     g_yh);
    cudaGetSymbolAddress((void**)&pooled, g_pooled);
    cudaGetSymbolAddress((void**)&wih,    g_wih);
    cudaGetSymbolAddress((void**)&wxh,    g_wxh);
    cudaGetSymbolAddress((void**)&wdh,    g_wdh);
    cudaGetSymbolAddress((void**)&woh,    g_woh);

    cudaFuncSetAttribute(k_gemmh<128,0>, cudaFuncAttributeMaxDynamicSharedMemorySize, SMEM_128);
    cudaFuncSetAttribute(k_gemmh<128,1>, cudaFuncAttributeMaxDynamicSharedMemorySize, SMEM_128);
    cudaFuncSetAttribute(k_gemmh<128,2>, cudaFuncAttributeMaxDynamicSharedMemorySize, SMEM_128);
    cudaFuncSetAttribute(k_gemmh<64,0>,  cudaFuncAttributeMaxDynamicSharedMemorySize, SMEM_64);

    // convert weights to fp16 (deterministic, every call)
    {
        int n1 = NLAYERS*2*DINNER*DMODEL;
        int n2 = NLAYERS*80*DINNER;
        int n3 = NLAYERS*DINNER*DTRANK;
        int n4 = NLAYERS*DMODEL*DINNER;
        k_f2h<<<(n1/4 + 255)/256, 256>>>(in_proj_w,  wih, n1);
        k_f2h<<<(n2/4 + 255)/256, 256>>>(x_proj_w,   wxh, n2);
        k_f2h<<<(n3/4 + 255)/256, 256>>>(dt_proj_w,  wdh, n3);
        k_f2h<<<(n4/4 + 255)/256, 256>>>(out_proj_w, woh, n4);
    }

    k_downsample<<<MREAL, 128>>>(x, conv_w, conv_b, h);

    const int convThreads = 256;
    const int convBlocks  = (MREAL*(DINNER/4) + convThreads - 1)/convThreads;

    for (int l = 0; l < NLAYERS; l++) {
        k_rmsnorm<__half><<<MREAL, 256>>>(h, norm_w + (size_t)l*DMODEL, hnh);

        // in_proj: xz[M,3072] = hnh[M,768] * Wih^T
        k_gemmh<128,0><<<dim3(2*DINNER/128, MPAD/128), 256, SMEM_128>>>(
            hnh, DMODEL, wih + (size_t)l*2*DINNER*DMODEL, DMODEL,
            xz, 2*DINNER, 2*DINNER, DMODEL, nullptr, nullptr, nullptr, nullptr);

        k_conv1d_silu<<<convBlocks, convThreads>>>(xz, conv1d_w + (size_t)l*DINNER*DCONV,
                                                   conv1d_b + (size_t)l*DINNER, u, uh);

        // x_proj: proj[M,80] (+fp16 copy) = uh[M,1536] * Wxh^T
        k_gemmh<64,0><<<dim3(2, MPAD/128), 256, SMEM_64>>>(
            uh, DINNER, wxh + (size_t)l*80*DINNER, DINNER,
            proj, 80, 80, DINNER, nullptr, nullptr, nullptr, projh);

        // dt_proj + fused softplus epilogue
        k_gemmh<128,2><<<dim3(DINNER/128, MPAD/128), 256, SMEM_128>>>(
            projh, 80, wdh + (size_t)l*DINNER*DTRANK, DTRANK,
            draw, DINNER, DINNER, DTRANK,
            dt_proj_b + (size_t)l*DINNER, u, delta, nullptr);

        k_scan<<<(BATCH*DINNER)/8, 128>>>(delta, draw, proj, u, xz,
                                          A_log + (size_t)l*DINNER*DSTATE,
                                          D_skip + (size_t)l*DINNER, yh);

        // out_proj (+residual): h += yh[M,1536] * Woh^T
        k_gemmh<128,1><<<dim3(DMODEL/128, MPAD/128), 256, SMEM_128>>>(
            yh, DINNER, woh + (size_t)l*DMODEL*DINNER, DINNER,
            h, DMODEL, DMODEL, DINNER, nullptr, nullptr, nullptr, nullptr);
    }

    k_rmsnorm<float><<<MREAL, 256>>>(h, norm_f_w, hn);
    k_zero<<<(BATCH*DMODEL + 255)/256, 256>>>(pooled, BATCH*DMODEL);
    k_pool<<<dim3(3, BATCH, 32), 256>>>(hn, pooled);
    k_head<<<BATCH, LATENT>>>(pooled, proj_w, proj_b, ln_w, ln_b, (float*)d_out);
}

// round 6
// speedup vs baseline: 1.7798x; 1.2221x over previous
#include <cuda_runtime.h>
#include <cstdint>
#include <cuda_fp16.h>
#include <mma.h>
#include <math.h>

using namespace nvcuda;

// ---------------- problem constants ----------------
#define BATCH   2
#define LIN     135000
#define DMODEL  768
#define NLAYERS 24
#define DINNER  1536
#define DSTATE  16
#define DCONV   4
#define DTRANK  48
#define KDS     32
#define SDS     32
#define LATENT  64
#define LSEQ    4218
#define MREAL   (BATCH*LSEQ)         // 8436
#define MPAD    8448                 // 66 * 128
#define NCH     66                   // scan chunks
#define CLEN    64                   // steps per chunk (66*64 = 4224 >= 4218)

// ---------------- scratch (device globals) ----------------
__device__ float  g_h    [MPAD*DMODEL];
__device__ float  g_hn   [MPAD*DMODEL];
__device__ __half g_hnh  [MPAD*DMODEL];
__device__ float  g_xz   [MPAD*2*DINNER];
__device__ float  g_u    [MPAD*DINNER];
__device__ __half g_uh   [MPAD*DINNER];
__device__ float  g_delta[MPAD*DINNER];
__device__ float  g_draw [MPAD*DINNER];
__device__ float  g_proj [MPAD*80];
__device__ __half g_projh[MPAD*80];
__device__ __half g_yh   [MPAD*DINNER];
__device__ float  g_pooled[BATCH*DMODEL];
__device__ __half g_wih[NLAYERS*2*DINNER*DMODEL];
__device__ __half g_wxh[NLAYERS*80*DINNER];
__device__ __half g_wdh[NLAYERS*DINNER*DTRANK];
__device__ __half g_woh[NLAYERS*DMODEL*DINNER];
// scan scratch
__device__ float  g_csum  [BATCH*DINNER*NCH];
__device__ float  g_hchunk[BATCH*DINNER*NCH*DSTATE];
__device__ float  g_h0    [BATCH*DINNER*NCH*DSTATE];

// ---------------- cp.async helpers ----------------
__device__ __forceinline__ void cp_async16(void* dst, const void* src, int bytes) {
    unsigned int d = (unsigned int)__cvta_generic_to_shared(dst);
    asm volatile("cp.async.cg.shared.global [%0], [%1], 16, %2;\n" :: "r"(d), "l"(src), "r"(bytes));
}
__device__ __forceinline__ void cp_commit() { asm volatile("cp.async.commit_group;\n"); }
template<int W> __device__ __forceinline__ void cp_wait() { asm volatile("cp.async.wait_group %0;\n" :: "n"(W)); }

// ---------------- fp32 -> fp16 convert ----------------
__global__ void k_f2h(const float* __restrict__ src, __half* __restrict__ dst, int n) {
    int i = (blockIdx.x*blockDim.x + threadIdx.x)*4;
    if (i + 3 < n) {
        float4 v = *(const float4*)(src + i);
        __half2* o = (__half2*)(dst + i);
        o[0] = __floats2half2_rn(v.x, v.y);
        o[1] = __floats2half2_rn(v.z, v.w);
    } else {
        for (; i < n; i++) dst[i] = __float2half(src[i]);
    }
}

// ---------------- downsample conv ----------------
__global__ void k_downsample(const float* __restrict__ x, const float* __restrict__ cw,
                             const float* __restrict__ cb, float* __restrict__ h) {
    int r = blockIdx.x;
    int b = r / LSEQ, t = r % LSEQ;
    __shared__ float xs[KDS];
    if (threadIdx.x < KDS) xs[threadIdx.x] = x[b*LIN + t*SDS + threadIdx.x];
    __syncthreads();
    for (int n = threadIdx.x; n < DMODEL; n += blockDim.x) {
        float acc = cb[n];
        const float* w = cw + n*KDS;
        #pragma unroll
        for (int k = 0; k < KDS; k++) acc += xs[k]*w[k];
        h[r*DMODEL + n] = acc;
    }
}

// ---------------- RMSNorm over 768 ----------------
template<typename T>
__global__ void k_rmsnorm(const float* __restrict__ in, const float* __restrict__ w,
                          T* __restrict__ out) {
    int r = blockIdx.x;
    __shared__ float red[256];
    const float* row = in + (size_t)r*DMODEL;
    float s = 0.f;
    #pragma unroll
    for (int i = 0; i < 3; i++) { float v = row[threadIdx.x + i*256]; s += v*v; }
    red[threadIdx.x] = s; __syncthreads();
    for (int o = 128; o > 0; o >>= 1) {
        if (threadIdx.x < o) red[threadIdx.x] += red[threadIdx.x + o];
        __syncthreads();
    }
    float inv = rsqrtf(red[0]/(float)DMODEL + 1e-5f);
    #pragma unroll
    for (int i = 0; i < 3; i++) {
        int d = threadIdx.x + i*256;
        out[(size_t)r*DMODEL + d] = (T)(row[d]*inv*w[d]);
    }
}

// ---------------- fp16 wmma GEMM: C[M,N] = A[M,K] * W[N,K]^T ----------------
#define BM_  128
#define BK_  64
#define LDH_ 72

template<int BN, int MODE>
__global__ __launch_bounds__(256) void k_gemmh(
    const __half* __restrict__ A, int lda,
    const __half* __restrict__ W, int ldw,
    float* __restrict__ C, int ldc, int N, int K,
    const float* __restrict__ db, const float* __restrict__ uu,
    float* __restrict__ dlt, __half* __restrict__ Ch)
{
    extern __shared__ char smraw[];
    __half* smem = (__half*)smraw;
    constexpr int ASZ = BM_ * LDH_;
    constexpr int BSZ = BN  * LDH_;
    __half* As0 = smem;
    __half* As1 = smem + ASZ;
    __half* Bs0 = smem + 2*ASZ;
    __half* Bs1 = smem + 2*ASZ + BSZ;

    const int tid = threadIdx.x;
    const int rowBase = blockIdx.y * BM_;
    const int n0 = blockIdx.x * BN;

    auto load_stage = [&](__half* Adst, __half* Bdst, int k0) {
        #pragma unroll
        for (int i = 0; i < 4; i++) {
            int idx = tid + i*256;
            int r = idx >> 3, c = (idx & 7)*8;
            int k = k0 + c;
            int bytes = (k < K) ? 16 : 0;
            const __half* src = bytes ? (A + (size_t)(rowBase + r)*lda + k) : A;
            cp_async16(Adst + r*LDH_ + c, src, bytes);
        }
        constexpr int BCH = BN*8/256;
        #pragma unroll
        for (int i = 0; i < BCH; i++) {
            int idx = tid + i*256;
            int r = idx >> 3, c = (idx & 7)*8;
            int k = k0 + c, n = n0 + r;
            int bytes = (n < N && k < K) ? 16 : 0;
            const __half* src = bytes ? (W + (size_t)n*ldw + k) : W;
            cp_async16(Bdst + r*LDH_ + c, src, bytes);
        }
    };

    constexpr int WARPS_N = (BN == 128) ? 4 : 2;
    constexpr int WARPS_M = 8/WARPS_N;
    constexpr int WTM = BM_/WARPS_M;
    constexpr int WTN = BN/WARPS_N;
    constexpr int MI = WTM/16, NI = WTN/16;
    const int warpId = tid >> 5;
    const int wm = warpId / WARPS_N;
    const int wn = warpId % WARPS_N;

    wmma::fragment<wmma::accumulator,16,16,16,float> cf[MI][NI];
    #pragma unroll
    for (int i = 0; i < MI; i++)
        #pragma unroll
        for (int j = 0; j < NI; j++) wmma::fill_fragment(cf[i][j], 0.f);

    const int ktiles = (K + BK_ - 1)/BK_;
    load_stage(As0, Bs0, 0);
    cp_commit();
    for (int kt = 0; kt < ktiles; kt++) {
        if (kt + 1 < ktiles) {
            load_stage((kt&1)?As0:As1, (kt&1)?Bs0:Bs1, (kt+1)*BK_);
            cp_commit();
            cp_wait<1>();
        } else {
            cp_wait<0>();
        }
        __syncthreads();
        const __half* a = (kt&1)?As1:As0;
        const __half* b = (kt&1)?Bs1:Bs0;
        #pragma unroll
        for (int kk = 0; kk < BK_; kk += 16) {
            wmma::fragment<wmma::matrix_a,16,16,16,__half,wmma::row_major> af[MI];
            wmma::fragment<wmma::matrix_b,16,16,16,__half,wmma::col_major> bf[NI];
            #pragma unroll
            for (int i = 0; i < MI; i++)
                wmma::load_matrix_sync(af[i], a + (wm*WTM + i*16)*LDH_ + kk, LDH_);
            #pragma unroll
            for (int j = 0; j < NI; j++)
                wmma::load_matrix_sync(bf[j], b + (wn*WTN + j*16)*LDH_ + kk, LDH_);
            #pragma unroll
            for (int i = 0; i < MI; i++)
                #pragma unroll
                for (int j = 0; j < NI; j++)
                    wmma::mma_sync(cf[i][j], af[i], bf[j], cf[i][j]);
        }
        __syncthreads();
    }

    constexpr int CLD = BN + 4;
    float* Cs = (float*)smraw;
    #pragma unroll
    for (int i = 0; i < MI; i++)
        #pragma unroll
        for (int j = 0; j < NI; j++)
            wmma::store_matrix_sync(Cs + (wm*WTM + i*16)*CLD + wn*WTN + j*16,
                                    cf[i][j], CLD, wmma::mem_row_major);
    __syncthreads();

    constexpr int IT = BM_*BN/(256*4);
    #pragma unroll
    for (int it = 0; it < IT; it++) {
        int idx = tid + it*256;
        int r = idx / (BN/4), c4 = (idx % (BN/4))*4;
        int n = n0 + c4;
        if (n >= N) continue;
        size_t g = (size_t)(rowBase + r)*ldc + n;
        float4 v = *(float4*)(Cs + r*CLD + c4);
        if constexpr (MODE == 1) {
            float4 o = *(float4*)(C + g);
            v.x += o.x; v.y += o.y; v.z += o.z; v.w += o.w;
            *(float4*)(C + g) = v;
        } else if constexpr (MODE == 2) {
            float4 bb = *(const float4*)(db + n);
            float4 uv = *(const float4*)(uu + g);
            float a0 = v.x + bb.x, a1 = v.y + bb.y, a2 = v.z + bb.z, a3 = v.w + bb.w;
            float d0 = (a0 > 20.f) ? a0 : log1pf(__expf(a0));
            float d1 = (a1 > 20.f) ? a1 : log1pf(__expf(a1));
            float d2 = (a2 > 20.f) ? a2 : log1pf(__expf(a2));
            float d3 = (a3 > 20.f) ? a3 : log1pf(__expf(a3));
            *(float4*)(dlt + g) = make_float4(d0, d1, d2, d3);
            *(float4*)(C + g)   = make_float4(d0*uv.x, d1*uv.y, d2*uv.z, d3*uv.w);
        } else {
            *(float4*)(C + g) = v;
            if (Ch) {
                __half2* o = (__half2*)(Ch + g);
                o[0] = __floats2half2_rn(v.x, v.y);
                o[1] = __floats2half2_rn(v.z, v.w);
            }
        }
    }
}

// ---------------- causal depthwise conv1d + silu ----------------
__global__ void k_conv1d_silu(const float* __restrict__ xz, const float* __restrict__ w,
                              const float* __restrict__ bias, float* __restrict__ u,
                              __half* __restrict__ uh) {
    int idx = blockIdx.x*blockDim.x + threadIdx.x;
    const int D4 = DINNER/4;
    if (idx >= MREAL*D4) return;
    int r  = idx / D4;
    int d4 = (idx % D4)*4;
    int t  = r % LSEQ;
    float4 w0 = *(const float4*)(w + (d4+0)*DCONV);
    float4 w1 = *(const float4*)(w + (d4+1)*DCONV);
    float4 w2 = *(const float4*)(w + (d4+2)*DCONV);
    float4 w3 = *(const float4*)(w + (d4+3)*DCONV);
    const float* w0p = &w0.x; const float* w1p = &w1.x;
    const float* w2p = &w2.x; const float* w3p = &w3.x;
    float4 acc = make_float4(bias[d4], bias[d4+1], bias[d4+2], bias[d4+3]);
    #pragma unroll
    for (int j = 0; j < DCONV; j++) {
        int tt = t + j - (DCONV-1);
        if (tt < 0) continue;
        float4 v = *(const float4*)(xz + (size_t)(r + j - (DCONV-1))*(2*DINNER) + d4);
        acc.x += v.x * w0p[j];
        acc.y += v.y * w1p[j];
        acc.z += v.z * w2p[j];
        acc.w += v.w * w3p[j];
    }
    acc.x = acc.x / (1.f + __expf(-acc.x));
    acc.y = acc.y / (1.f + __expf(-acc.y));
    acc.z = acc.z / (1.f + __expf(-acc.z));
    acc.w = acc.w / (1.f + __expf(-acc.w));
    *(float4*)(u + (size_t)r*DINNER + d4) = acc;
    __half2* o = (__half2*)(uh + (size_t)r*DINNER + d4);
    o[0] = __floats2half2_rn(acc.x, acc.y);
    o[1] = __floats2half2_rn(acc.z, acc.w);
}

// ---------------- chunked selective scan (3 passes) ----------------
// Pass 1: per (chain, chunk): local state h_local[16] and sum of delta.
__global__ __launch_bounds__(256) void k_scan1(
    const float* __restrict__ delta, const float* __restrict__ du,
    const float* __restrict__ proj,  const float* __restrict__ Alog,
    float* __restrict__ csum, float* __restrict__ hchunk)
{
    int grp = threadIdx.x >> 4, s = threadIdx.x & 15;
    int chain = blockIdx.x*16 + grp;
    int c = blockIdx.y;
    int b = chain / DINNER, d = chain % DINNER;
    float Av = -expf(Alog[d*DSTATE + s]);
    int t0 = c*CLEN, t1 = t0 + CLEN; if (t1 > LSEQ) t1 = LSEQ;
    int rbase = b*LSEQ;
    float h = 0.f, cum = 0.f;
    for (int t = t0; t < t1; t++) {
        size_t r = (size_t)(rbase + t);
        float dl  = delta[r*DINNER + d];
        float dlu = du  [r*DINNER + d];
        float bv  = proj[r*80 + 48 + s];
        h = __expf(dl*Av)*h + dlu*bv;
        cum += dl;
    }
    size_t gidx = (size_t)chain*NCH + c;
    if (s == 0) csum[gidx] = cum;
    hchunk[gidx*DSTATE + s] = h;
}

// Pass 2: sequential combine over chunks -> chunk-initial states h0.
__global__ __launch_bounds__(256) void k_scan2(
    const float* __restrict__ Alog, const float* __restrict__ csum,
    const float* __restrict__ hchunk, float* __restrict__ h0a)
{
    int idx = blockIdx.x*blockDim.x + threadIdx.x;
    int chain = idx >> 4, s = idx & 15;
    if (chain >= BATCH*DINNER) return;
    int d = chain % DINNER;
    float Av = -expf(Alog[d*DSTATE + s]);
    float h0 = 0.f;
    size_t base = (size_t)chain*NCH;
    for (int c = 0; c < NCH; c++) {
        h0a[(base + c)*DSTATE + s] = h0;
        float e = __expf(csum[base + c]*Av);
        h0 = e*h0 + hchunk[(base + c)*DSTATE + s];
    }
}

// Pass 3: recompute within chunk with injected h0; produce gated output.
__global__ __launch_bounds__(256) void k_scan3(
    const float* __restrict__ delta, const float* __restrict__ du,
    const float* __restrict__ proj,  const float* __restrict__ u,
    const float* __restrict__ xz,    const float* __restrict__ Alog,
    const float* __restrict__ Dskip, const float* __restrict__ h0a,
    __half* __restrict__ y)
{
    int grp = threadIdx.x >> 4, s = threadIdx.x & 15;
    int chain = blockIdx.x*16 + grp;
    int c = blockIdx.y;
    int b = chain / DINNER, d = chain % DINNER;
    float Av = -expf(Alog[d*DSTATE + s]);
    float Dv = Dskip[d];
    bool lane0 = (s == 0);
    int t0 = c*CLEN, t1 = t0 + CLEN; if (t1 > LSEQ) t1 = LSEQ;
    int rbase = b*LSEQ;
    float h0 = h0a[((size_t)chain*NCH + c)*DSTATE + s];
    float hl = 0.f, D = 1.f;
    for (int t = t0; t < t1; t++) {
        size_t r = (size_t)(rbase + t);
        float dl  = delta[r*DINNER + d];
        float dlu = du  [r*DINNER + d];
        float bv  = proj[r*80 + 48 + s];
        float cv  = proj[r*80 + 64 + s];
        float e = __expf(dl*Av);
        hl = e*hl + dlu*bv;
        D *= e;
        float yv = (hl + D*h0)*cv;
        yv += __shfl_xor_sync(0xffffffffu, yv, 8);
        yv += __shfl_xor_sync(0xffffffffu, yv, 4);
        yv += __shfl_xor_sync(0xffffffffu, yv, 2);
        yv += __shfl_xor_sync(0xffffffffu, yv, 1);
        if (lane0) {
            float uvv = u [r*DINNER + d];
            float z   = xz[r*2*DINNER + DINNER + d];
            float sig = 1.f/(1.f + __expf(-z));
            y[r*DINNER + d] = __float2half((yv + uvv*Dv)*z*sig);
        }
    }
}

// ---------------- pooling + head ----------------
__global__ void k_zero(float* p, int n) {
    int i = blockIdx.x*blockDim.x + threadIdx.x;
    if (i < n) p[i] = 0.f;
}

__global__ void k_pool(const float* __restrict__ hn, float* __restrict__ pooled) {
    int d  = blockIdx.x*blockDim.x + threadIdx.x;
    int b  = blockIdx.y;
    int tc = blockIdx.z;
    int t0 = tc*132, t1 = t0 + 132; if (t1 > LSEQ) t1 = LSEQ;
    float acc = 0.f;
    for (int t = t0; t < t1; t++) acc += hn[(size_t)(b*LSEQ + t)*DMODEL + d];
    atomicAdd(&pooled[b*DMODEL + d], acc);
}

__global__ void k_head(const float* __restrict__ pooled, const float* __restrict__ pw,
                       const float* __restrict__ pb, const float* __restrict__ lw,
                       const float* __restrict__ lb, float* __restrict__ out) {
    int b = blockIdx.x, j = threadIdx.x;
    __shared__ float zs[LATENT];
    const float* pr = pooled + b*DMODEL;
    const float* wr = pw + j*DMODEL;
    float acc = 0.f;
    for (int d = 0; d < DMODEL; d++) acc += pr[d]*wr[d];
    float zed = acc*(1.f/(float)LSEQ) + pb[j];
    zs[j] = zed; __syncthreads();
    float mu = 0.f;
    for (int i = 0; i < LATENT; i++) mu += zs[i];
    mu /= LATENT;
    float var = 0.f;
    for (int i = 0; i < LATENT; i++) { float dd = zs[i]-mu; var += dd*dd; }
    var /= LATENT;
    out[b*LATENT + j] = (zed - mu)*rsqrtf(var + 1e-5f)*lw[j] + lb[j];
}

// ---------------- host orchestration ----------------
#define SMEM_128 (2*(128*LDH_ + 128*LDH_)*2)
#define SMEM_64  (2*(128*LDH_ +  64*LDH_)*2)

extern "C" void kernel_launch(void* const* d_in, const int* in_sizes, int n_in,
                              void* d_out, int out_size) {
    const float* x         = (const float*)d_in[0];
    const float* conv_w    = (const float*)d_in[1];
    const float* conv_b    = (const float*)d_in[2];
    const float* norm_w    = (const float*)d_in[3];
    const float* in_proj_w = (const float*)d_in[4];
    const float* conv1d_w  = (const float*)d_in[5];
    const float* conv1d_b  = (const float*)d_in[6];
    const float* x_proj_w  = (const float*)d_in[7];
    const float* dt_proj_w = (const float*)d_in[8];
    const float* dt_proj_b = (const float*)d_in[9];
    const float* A_log     = (const float*)d_in[10];
    const float* D_skip    = (const float*)d_in[11];
    const float* out_proj_w= (const float*)d_in[12];
    const float* norm_f_w  = (const float*)d_in[13];
    const float* proj_w    = (const float*)d_in[14];
    const float* proj_b    = (const float*)d_in[15];
    const float* ln_w      = (const float*)d_in[16];
    const float* ln_b      = (const float*)d_in[17];

    float  *h, *hn, *xz, *u, *delta, *draw, *proj, *pooled, *csum, *hchunk, *h0a;
    __half *hnh, *uh, *projh, *yh, *wih, *wxh, *wdh, *woh;
    cudaGetSymbolAddress((void**)&h,      g_h);
    cudaGetSymbolAddress((void**)&hn,     g_hn);
    cudaGetSymbolAddress((void**)&hnh,    g_hnh);
    cudaGetSymbolAddress((void**)&xz,     g_xz);
    cudaGetSymbolAddress((void**)&u,      g_u);
    cudaGetSymbolAddress((void**)&uh,     g_uh);
    cudaGetSymbolAddress((void**)&delta,  g_delta);
    cudaGetSymbolAddress((void**)&draw,   g_draw);
    cudaGetSymbolAddress((void**)&proj,   g_proj);
    cudaGetSymbolAddress((void**)&projh,  g_projh);
    cudaGetSymbolAddress((void**)&yh,     g_yh);
    cudaGetSymbolAddress((void**)&pooled, g_pooled);
    cudaGetSymbolAddress((void**)&wih,    g_wih);
    cudaGetSymbolAddress((void**)&wxh,    g_wxh);
    cudaGetSymbolAddress((void**)&wdh,    g_wdh);
    cudaGetSymbolAddress((void**)&woh,    g_woh);
    cudaGetSymbolAddress((void**)&csum,   g_csum);
    cudaGetSymbolAddress((void**)&hchunk, g_hchunk);
    cudaGetSymbolAddress((void**)&h0a,    g_h0);

    cudaFuncSetAttribute(k_gemmh<128,0>, cudaFuncAttributeMaxDynamicSharedMemorySize, SMEM_128);
    cudaFuncSetAttribute(k_gemmh<128,1>, cudaFuncAttributeMaxDynamicSharedMemorySize, SMEM_128);
    cudaFuncSetAttribute(k_gemmh<128,2>, cudaFuncAttributeMaxDynamicSharedMemorySize, SMEM_128);
    cudaFuncSetAttribute(k_gemmh<64,0>,  cudaFuncAttributeMaxDynamicSharedMemorySize, SMEM_64);

    // convert weights to fp16
    {
        int n1 = NLAYERS*2*DINNER*DMODEL;
        int n2 = NLAYERS*80*DINNER;
        int n3 = NLAYERS*DINNER*DTRANK;
        int n4 = NLAYERS*DMODEL*DINNER;
        k_f2h<<<(n1/4 + 255)/256, 256>>>(in_proj_w,  wih, n1);
        k_f2h<<<(n2/4 + 255)/256, 256>>>(x_proj_w,   wxh, n2);
        k_f2h<<<(n3/4 + 255)/256, 256>>>(dt_proj_w,  wdh, n3);
        k_f2h<<<(n4/4 + 255)/256, 256>>>(out_proj_w, woh, n4);
    }

    k_downsample<<<MREAL, 128>>>(x, conv_w, conv_b, h);

    const int convThreads = 256;
    const int convBlocks  = (MREAL*(DINNER/4) + convThreads - 1)/convThreads;
    const dim3 scanGrid(BATCH*DINNER/16, NCH);

    for (int l = 0; l < NLAYERS; l++) {
        const float* Al = A_log + (size_t)l*DINNER*DSTATE;

        k_rmsnorm<__half><<<MREAL, 256>>>(h, norm_w + (size_t)l*DMODEL, hnh);

        // in_proj: xz[M,3072] = hnh[M,768] * Wih^T
        k_gemmh<128,0><<<dim3(2*DINNER/128, MPAD/128), 256, SMEM_128>>>(
            hnh, DMODEL, wih + (size_t)l*2*DINNER*DMODEL, DMODEL,
            xz, 2*DINNER, 2*DINNER, DMODEL, nullptr, nullptr, nullptr, nullptr);

        k_conv1d_silu<<<convBlocks, convThreads>>>(xz, conv1d_w + (size_t)l*DINNER*DCONV,
                                                   conv1d_b + (size_t)l*DINNER, u, uh);

        // x_proj: proj[M,80] (+fp16 copy)
        k_gemmh<64,0><<<dim3(2, MPAD/128), 256, SMEM_64>>>(
            uh, DINNER, wxh + (size_t)l*80*DINNER, DINNER,
            proj, 80, 80, DINNER, nullptr, nullptr, nullptr, projh);

        // dt_proj + fused softplus
        k_gemmh<128,2><<<dim3(DINNER/128, MPAD/128), 256, SMEM_128>>>(
            projh, 80, wdh + (size_t)l*DINNER*DTRANK, DTRANK,
            draw, DINNER, DINNER, DTRANK,
            dt_proj_b + (size_t)l*DINNER, u, delta, nullptr);

        // chunked parallel scan
        k_scan1<<<scanGrid, 256>>>(delta, draw, proj, Al, csum, hchunk);
        k_scan2<<<(BATCH*DINNER*DSTATE)/256, 256>>>(Al, csum, hchunk, h0a);
        k_scan3<<<scanGrid, 256>>>(delta, draw, proj, u, xz, Al,
                                   D_skip + (size_t)l*DINNER, h0a, yh);

        // out_proj (+residual): h += yh[M,1536] * Woh^T
        k_gemmh<128,1><<<dim3(DMODEL/128, MPAD/128), 256, SMEM_128>>>(
            yh, DINNER, woh + (size_t)l*DMODEL*DINNER, DINNER,
            h, DMODEL, DMODEL, DINNER, nullptr, nullptr, nullptr, nullptr);
    }

    k_rmsnorm<float><<<MREAL, 256>>>(h, norm_f_w, hn);
    k_zero<<<(BATCH*DMODEL + 255)/256, 256>>>(pooled, BATCH*DMODEL);
    k_pool<<<dim3(3, BATCH, 32), 256>>>(hn, pooled);
    k_head<<<BATCH, LATENT>>>(pooled, proj_w, proj_b, ln_w, ln_b, (float*)d_out);
}